// round 17
// baseline (speedup 1.0000x reference)
#include <cuda_runtime.h>

// RWKV WKV single-pass warp-scan, v10: warp-specialized scan/epilogue.
//   a_t = d_t a_{t-1} + ek_t v_t ; b_t = d_t b_{t-1} + ek_t
//   out = sigmoid(r) * a/(b+eps),  d = exp(-exp(w)), ek = exp(k)
//
// Geometry as v8/v9 (114.7us best): CBLK=32 (128B runs), TTILE=64, 512 thr,
// double-buffered smem, 1 barrier/iter. New: after the barrier, warps 0-7 run
// a serial-8 width-8 KS scan (120 SHFL/CTA-iter vs 288) while warps 8-15 do
// the pipelined readback+sigmoid+store of tile it-1 and own the r loads.

#define B_      8
#define T_      4096
#define C_      1024
#define CBLK    32
#define TTILE   64
#define NITER   (T_ / TTILE)      // 64
#define THREADS 512
#define SROW    68                // mult of 4 (16B-aligned rows) + skew
#define REGF    (CBLK * SROW)     // 2176 floats per region
#define SMEMB   (8 * REGF * 4)    // d,e,x,so x 2 buffers = 69632 B
#define WKV_EPS 1e-6f

// v8-verified skewed transpose address.
__device__ __forceinline__ int saddr(int ch, int t) {
    return ch * SROW + ((t + 4 * (ch >> 2)) & 63);
}

__global__ void __launch_bounds__(THREADS, 2)
wkv_scan10(const float4* __restrict__ r, const float4* __restrict__ w,
           const float4* __restrict__ k, const float4* __restrict__ v,
           float4* __restrict__ out) {
    extern __shared__ float S[];

    const int tid  = threadIdx.x;
    const int lane = tid & 31;
    const int wid  = tid >> 5;            // 0..15
    const int cl4  = tid & 7;             // loader: float4 column (128B run)
    const int tl   = tid >> 3;            // loader: t-row 0..63

    const int b  = blockIdx.x >> 5;               // 8 batches
    const int c0 = (blockIdx.x & 31) * CBLK;      // 32 channel blocks
    const int rowF4 = C_ / 4;                     // 256 float4 per time row
    const int gco   = (b * T_) * rowF4 + (c0 >> 2) + cl4;

    // Scan role (warps 0..7): 8-lane segment owns one channel, lane owns 8 t.
    const bool isScan = (wid < 8);
    const int  seg = lane >> 3;           // 0..3
    const int  sl  = lane & 7;            // 0..7
    const int  chS = 4 * wid + seg;       // valid when isScan
    const int  pS0 = saddr(chS, 8 * sl);          // first 4 timesteps
    const int  pS1 = saddr(chS, 8 * sl + 4);      // next 4 (wrap-safe, aligned)

    // Epilogue role (warps 8..15): readback+store; owns r loads.
    const int ep    = tid - 256;          // valid when !isScan: 0..255
    const int cl4e  = ep & 7;
    const int tle   = ep >> 3;            // 0..31 (rows tle, tle+32)
    const int gcoE  = (b * T_) * rowF4 + (c0 >> 2) + cl4e;

    // Prefetch tile 0 (raw w,k,v; distributed over all threads).
    float4 pw = __ldcs(&w[gco + tl * rowF4]);
    float4 pk = __ldcs(&k[gco + tl * rowF4]);
    float4 pv = __ldcs(&v[gco + tl * rowF4]);

    float aC = 0.f, bC = 0.f;             // scan carries (scan warps only)
    float4 prOld[2], prNew[2];            // r tiles (epilogue warps only)

    for (int it = 0; it < NITER; ++it) {
        const int bf = it & 1;
        float* sd = S + (0 + bf) * REGF;   // decay d
        float* se = S + (2 + bf) * REGF;   // ek
        float* sx = S + (4 + bf) * REGF;   // ek*v
        float* so = S + (6 + bf) * REGF;
        float* soPrev = S + (6 + (1 - bf)) * REGF;

        // ---- convert + stage current tile (all threads) ----
#pragma unroll
        for (int j = 0; j < 4; ++j) {
            const int a = saddr(4 * cl4 + j, tl);
            const float dd = __expf(-__expf(((const float*)&pw)[j]));
            const float ek = __expf(((const float*)&pk)[j]);
            sd[a] = dd;
            se[a] = ek;
            sx[a] = ek * ((const float*)&pv)[j];
        }
        // ---- prefetch next raw tile (all threads) ----
        if (it + 1 < NITER) {
            const int g = gco + ((it + 1) * TTILE + tl) * rowF4;
            pw = __ldcs(&w[g]);  pk = __ldcs(&k[g]);  pv = __ldcs(&v[g]);
        }
        __syncthreads();   // staging visible; previous generation consumed

        if (isScan) {
            // ---- serial-8, width-8 Kogge-Stone over segment lanes ----
            const float4 dA = *(const float4*)&sd[pS0];
            const float4 dB = *(const float4*)&sd[pS1];
            const float4 eA = *(const float4*)&se[pS0];
            const float4 eB = *(const float4*)&se[pS1];
            const float4 xA = *(const float4*)&sx[pS0];
            const float4 xB = *(const float4*)&sx[pS1];
            float d[8], e[8], x[8];
#pragma unroll
            for (int i = 0; i < 4; ++i) {
                d[i] = ((const float*)&dA)[i];  d[i + 4] = ((const float*)&dB)[i];
                e[i] = ((const float*)&eA)[i];  e[i + 4] = ((const float*)&eB)[i];
                x[i] = ((const float*)&xA)[i];  x[i + 4] = ((const float*)&xB)[i];
            }

            // local composition tree of 8 steps
            float Dp[4], Ap[4], Bp[4];
#pragma unroll
            for (int i = 0; i < 4; ++i) {
                Dp[i] = d[2 * i] * d[2 * i + 1];
                Ap[i] = fmaf(x[2 * i], d[2 * i + 1], x[2 * i + 1]);
                Bp[i] = fmaf(e[2 * i], d[2 * i + 1], e[2 * i + 1]);
            }
            const float D0123 = Dp[0] * Dp[1];
            const float A0123 = fmaf(Ap[0], Dp[1], Ap[1]);
            const float B0123 = fmaf(Bp[0], Dp[1], Bp[1]);
            const float D4567 = Dp[2] * Dp[3];
            const float A4567 = fmaf(Ap[2], Dp[3], Ap[3]);
            const float B4567 = fmaf(Bp[2], Dp[3], Bp[3]);
            float D  = D0123 * D4567;
            float A  = fmaf(A0123, D4567, A4567);
            float Bv = fmaf(B0123, D4567, B4567);

            // width-8 inclusive KS
#pragma unroll
            for (int s = 1; s < 8; s <<= 1) {
                const float Ds = __shfl_up_sync(0xffffffffu, D, s, 8);
                const float As = __shfl_up_sync(0xffffffffu, A, s, 8);
                const float Bs = __shfl_up_sync(0xffffffffu, Bv, s, 8);
                if (sl >= s) {
                    A  = fmaf(As, D, A);
                    Bv = fmaf(Bs, D, Bv);
                    D *= Ds;
                }
            }
            // exclusive prefix
            float Dx = __shfl_up_sync(0xffffffffu, D, 1, 8);
            float Ax = __shfl_up_sync(0xffffffffu, A, 1, 8);
            float Bx = __shfl_up_sync(0xffffffffu, Bv, 1, 8);
            if (sl == 0) { Dx = 1.f; Ax = 0.f; Bx = 0.f; }
            float ain = fmaf(aC, Dx, Ax);
            float bin = fmaf(bC, Dx, Bx);

            // carry from segment lane 7 inclusive aggregate
            const float D7 = __shfl_sync(0xffffffffu, D, 7, 8);
            const float A7 = __shfl_sync(0xffffffffu, A, 7, 8);
            const float B7 = __shfl_sync(0xffffffffu, Bv, 7, 8);
            aC = fmaf(aC, D7, A7);
            bC = fmaf(bC, D7, B7);

            // replay 8 steps, emit a/(b+eps) as two STS.128
            float4 o0, o1;
#pragma unroll
            for (int i = 0; i < 4; ++i) {
                ain = fmaf(ain, d[i], x[i]);
                bin = fmaf(bin, d[i], e[i]);
                ((float*)&o0)[i] = __fdividef(ain, bin + WKV_EPS);
            }
#pragma unroll
            for (int i = 0; i < 4; ++i) {
                ain = fmaf(ain, d[i + 4], x[i + 4]);
                bin = fmaf(bin, d[i + 4], e[i + 4]);
                ((float*)&o1)[i] = __fdividef(ain, bin + WKV_EPS);
            }
            *(float4*)&so[pS0] = o0;
            *(float4*)&so[pS1] = o1;
        } else {
            // ---- epilogue: r loads for THIS tile + readback of tile it-1 ----
#pragma unroll
            for (int h = 0; h < 2; ++h)
                prNew[h] = __ldcs(&r[gcoE + (it * TTILE + tle + h * 32) * rowF4]);
            if (it > 0) {
#pragma unroll
                for (int h = 0; h < 2; ++h) {
                    const int t = tle + h * 32;
                    float4 o;
#pragma unroll
                    for (int j = 0; j < 4; ++j)
                        ((float*)&o)[j] = soPrev[saddr(4 * cl4e + j, t)];
                    o.x = __fdividef(o.x, 1.f + __expf(-prOld[h].x));
                    o.y = __fdividef(o.y, 1.f + __expf(-prOld[h].y));
                    o.z = __fdividef(o.z, 1.f + __expf(-prOld[h].z));
                    o.w = __fdividef(o.w, 1.f + __expf(-prOld[h].w));
                    __stcs(&out[gcoE + ((it - 1) * TTILE + t) * rowF4], o);
                }
            }
            prOld[0] = prNew[0];
            prOld[1] = prNew[1];
        }
    }

    // ---- final readback: tile NITER-1 in buffer (NITER-1)&1 ----
    __syncthreads();
    if (!isScan) {
        float* soLast = S + (6 + ((NITER - 1) & 1)) * REGF;
#pragma unroll
        for (int h = 0; h < 2; ++h) {
            const int t = tle + h * 32;
            float4 o;
#pragma unroll
            for (int j = 0; j < 4; ++j)
                ((float*)&o)[j] = soLast[saddr(4 * cl4e + j, t)];
            o.x = __fdividef(o.x, 1.f + __expf(-prOld[h].x));
            o.y = __fdividef(o.y, 1.f + __expf(-prOld[h].y));
            o.z = __fdividef(o.z, 1.f + __expf(-prOld[h].z));
            o.w = __fdividef(o.w, 1.f + __expf(-prOld[h].w));
            __stcs(&out[gcoE + ((NITER - 1) * TTILE + t) * rowF4], o);
        }
    }
}

extern "C" void kernel_launch(void* const* d_in, const int* in_sizes, int n_in,
                              void* d_out, int out_size) {
    const float4* r = (const float4*)d_in[0];
    const float4* w = (const float4*)d_in[1];
    const float4* k = (const float4*)d_in[2];
    const float4* v = (const float4*)d_in[3];
    float4* o = (float4*)d_out;

    cudaFuncSetAttribute(wkv_scan10,
                         cudaFuncAttributeMaxDynamicSharedMemorySize, SMEMB);
    const int grid = B_ * (C_ / CBLK);    // 256 CTAs
    wkv_scan10<<<grid, THREADS, SMEMB>>>(r, w, k, v, o);
}